// round 1
// baseline (speedup 1.0000x reference)
#include <cuda_runtime.h>
#include <cuda_bf16.h>
#include <math.h>

// ---------------------------------------------------------------------------
// ManifoldTransformer: 4-layer pre-norm GPT-2 style forward pass, fp32.
// B=2, S=1024, D=512, H=8 (dk=64), DFF=2048, L=4, V=50257.
// Rows = B*S = 2048 tokens.
// ---------------------------------------------------------------------------

#define NROWS 2048
#define DMODEL 512
#define NHEAD 8
#define DK 64
#define DFF 2048
#define NLAYER 4
#define VOCAB 50257
#define SEQ 1024

// Scratch activations (device globals: allocation-free).
__device__ float g_x [NROWS * DMODEL];
__device__ float g_h [NROWS * DMODEL];
__device__ float g_q [NROWS * DMODEL];
__device__ float g_k [NROWS * DMODEL];
__device__ float g_v [NROWS * DMODEL];
__device__ float g_ao[NROWS * DMODEL];
__device__ float g_ff[NROWS * DFF];

// ---------------------------------------------------------------------------
// Embedding gather + positional add.  grid=2048 blocks, 128 threads.
// ---------------------------------------------------------------------------
__global__ void embed_kernel(const int* __restrict__ tok,
                             const float* __restrict__ emb,
                             const float* __restrict__ pos,
                             float* __restrict__ x)
{
    int row = blockIdx.x;
    int tid = threadIdx.x;
    int t = tok[row];
    int s = row & (SEQ - 1);
    float4 e = *(const float4*)&emb[t * DMODEL + tid * 4];
    float4 p = *(const float4*)&pos[s * DMODEL + tid * 4];
    e.x += p.x; e.y += p.y; e.z += p.z; e.w += p.w;
    *(float4*)&x[row * DMODEL + tid * 4] = e;
}

// ---------------------------------------------------------------------------
// LayerNorm over D=512.  One block (128 threads) per row; each thread holds 4.
// ---------------------------------------------------------------------------
__global__ void ln_kernel(const float* __restrict__ x,
                          const float* __restrict__ g,
                          const float* __restrict__ b,
                          float* __restrict__ y)
{
    __shared__ float red[4];
    __shared__ float bc;
    int row = blockIdx.x;
    int tid = threadIdx.x;
    int lane = tid & 31, w = tid >> 5;

    float4 v = *(const float4*)&x[row * DMODEL + tid * 4];

    float s = v.x + v.y + v.z + v.w;
    #pragma unroll
    for (int o = 16; o; o >>= 1) s += __shfl_xor_sync(0xffffffffu, s, o);
    if (lane == 0) red[w] = s;
    __syncthreads();
    if (tid == 0) bc = (red[0] + red[1] + red[2] + red[3]) * (1.0f / 512.0f);
    __syncthreads();
    float mean = bc;

    float dx = v.x - mean, dy = v.y - mean, dz = v.z - mean, dw = v.w - mean;
    float s2 = dx*dx + dy*dy + dz*dz + dw*dw;
    #pragma unroll
    for (int o = 16; o; o >>= 1) s2 += __shfl_xor_sync(0xffffffffu, s2, o);
    __syncthreads();               // ensure everyone read bc before re-use of red
    if (lane == 0) red[w] = s2;
    __syncthreads();
    if (tid == 0) bc = rsqrtf((red[0] + red[1] + red[2] + red[3]) * (1.0f / 512.0f) + 1e-5f);
    __syncthreads();
    float inv = bc;

    float4 gg = *(const float4*)&g[tid * 4];
    float4 bb = *(const float4*)&b[tid * 4];
    float4 o4;
    o4.x = dx * inv * gg.x + bb.x;
    o4.y = dy * inv * gg.y + bb.y;
    o4.z = dz * inv * gg.z + bb.z;
    o4.w = dw * inv * gg.w + bb.w;
    *(float4*)&y[row * DMODEL + tid * 4] = o4;
}

// ---------------------------------------------------------------------------
// SGEMM (NT):  C[M,N] = A[M,K] @ B[N,K]^T + bias  (+gelu) (+residual)
// Both operands K-contiguous (torch Linear layout).
// Tile: BM=128, BN=64, BK=32. 128 threads, 8x8 microtile each.
// M % 128 == 0, K % 32 == 0 guaranteed; N guarded.
// ---------------------------------------------------------------------------
template<bool DO_GELU, bool DO_RES>
__global__ __launch_bounds__(128)
void sgemm_nt(const float* __restrict__ A, const float* __restrict__ Bm,
              const float* __restrict__ bias, const float* __restrict__ R,
              float* __restrict__ C, int M, int N, int K)
{
    __shared__ float As[32][129];   // [k][m], padded: conflict-free transposed stores
    __shared__ float Bs[32][65];    // [k][n]

    const int tid = threadIdx.x;
    const int m0 = blockIdx.y * 128;
    const int n0 = blockIdx.x * 64;
    const int ty = tid >> 3;        // 0..15 -> M direction
    const int tx = tid & 7;         // 0..7  -> N direction

    float acc[8][8];
    #pragma unroll
    for (int i = 0; i < 8; i++)
        #pragma unroll
        for (int j = 0; j < 8; j++) acc[i][j] = 0.0f;

    for (int kb = 0; kb < K; kb += 32) {
        // A tile: 128 rows x 32 k  = 1024 float4 / 128 thr = 8 each
        #pragma unroll
        for (int t = 0; t < 8; t++) {
            int idx = tid + t * 128;
            int row = idx >> 3, k4 = (idx & 7) << 2;
            float4 va = *(const float4*)&A[(m0 + row) * K + kb + k4];
            As[k4 + 0][row] = va.x;
            As[k4 + 1][row] = va.y;
            As[k4 + 2][row] = va.z;
            As[k4 + 3][row] = va.w;
        }
        // B tile: 64 rows x 32 k = 512 float4 / 128 thr = 4 each
        #pragma unroll
        for (int t = 0; t < 4; t++) {
            int idx = tid + t * 128;
            int row = idx >> 3, k4 = (idx & 7) << 2;
            float4 vb;
            if (n0 + row < N) vb = *(const float4*)&Bm[(n0 + row) * K + kb + k4];
            else              vb = make_float4(0.f, 0.f, 0.f, 0.f);
            Bs[k4 + 0][row] = vb.x;
            Bs[k4 + 1][row] = vb.y;
            Bs[k4 + 2][row] = vb.z;
            Bs[k4 + 3][row] = vb.w;
        }
        __syncthreads();

        #pragma unroll
        for (int kk = 0; kk < 32; kk++) {
            float a[8], bb[8];
            #pragma unroll
            for (int i = 0; i < 8; i++) a[i]  = As[kk][ty * 8 + i];
            #pragma unroll
            for (int j = 0; j < 8; j++) bb[j] = Bs[kk][tx * 8 + j];
            #pragma unroll
            for (int i = 0; i < 8; i++)
                #pragma unroll
                for (int j = 0; j < 8; j++)
                    acc[i][j] = fmaf(a[i], bb[j], acc[i][j]);
        }
        __syncthreads();
    }

    #pragma unroll
    for (int i = 0; i < 8; i++) {
        int gm = m0 + ty * 8 + i;
        #pragma unroll
        for (int j = 0; j < 8; j++) {
            int gn = n0 + tx * 8 + j;
            if (gn < N) {
                float vv = acc[i][j] + bias[gn];
                if (DO_GELU) vv = 0.5f * vv * (1.0f + erff(vv * 0.70710678118654752f));
                if (DO_RES)  vv += R[gm * N + gn];
                C[gm * N + gn] = vv;
            }
        }
    }
}

// ---------------------------------------------------------------------------
// Flash-style causal attention.  grid = (qb=16, bh=16), 256 threads.
// Each CTA: 64 query rows of one (b,h). Thread t: row r=t/4, seg=t%4.
// Q row cached in registers; online softmax; exp de-duplicated per row
// (each thread computes 16 exps, p shared through smem within the warp).
// ---------------------------------------------------------------------------
#define ATTN_PAD 68
#define ATTN_SMEM_BYTES (3 * 64 * ATTN_PAD * 4)

__global__ __launch_bounds__(256)
void attn_kernel(const float* __restrict__ qg, const float* __restrict__ kg,
                 const float* __restrict__ vg, float* __restrict__ og)
{
    extern __shared__ float sm[];
    float* Ks = sm;
    float* Vs = sm + 64 * ATTN_PAD;
    float* Ss = sm + 2 * 64 * ATTN_PAD;

    const int qb = blockIdx.x, bh = blockIdx.y;
    const int b = bh >> 3, h = bh & 7;
    const int tid = threadIdx.x;
    const int r = tid >> 2, seg = tid & 3;
    const int rowbase = b << 10;
    const int col0 = h << 6;
    const int qglob = (qb << 6) + r;

    // Q row into registers (64 floats)
    float qreg[64];
    {
        const float* qptr = &qg[(rowbase + qglob) * DMODEL + col0];
        #pragma unroll
        for (int i = 0; i < 16; i++) {
            float4 t = *(const float4*)&qptr[i * 4];
            qreg[i*4+0] = t.x; qreg[i*4+1] = t.y; qreg[i*4+2] = t.z; qreg[i*4+3] = t.w;
        }
    }

    float m_r = -3e38f, l_r = 0.0f;
    float oacc[16];
    #pragma unroll
    for (int i = 0; i < 16; i++) oacc[i] = 0.0f;

    for (int kb = 0; kb <= qb; kb++) {
        __syncthreads();   // protect K/V/S reuse from previous iteration
        for (int i = tid; i < 1024; i += 256) {
            int rr = i >> 4, c4 = (i & 15) << 2;
            int g = (rowbase + (kb << 6) + rr) * DMODEL + col0 + c4;
            float4 tk = *(const float4*)&kg[g];
            float4 tv = *(const float4*)&vg[g];
            *(float4*)&Ks[rr * ATTN_PAD + c4] = tk;
            *(float4*)&Vs[rr * ATTN_PAD + c4] = tv;
        }
        __syncthreads();

        // scores for this thread's 16 key cols: kc = jj*4 + seg
        float sc[16];
        #pragma unroll 4
        for (int jj = 0; jj < 16; jj++) {
            int kc = (jj << 2) + seg;
            const float* kptr = &Ks[kc * ATTN_PAD];
            float a0 = 0.0f;
            #pragma unroll
            for (int d = 0; d < 64; d++) a0 = fmaf(qreg[d], kptr[d], a0);
            a0 *= 0.125f;
            if ((kb << 6) + kc > qglob) a0 = -3e38f;
            sc[jj] = a0;
        }

        // row max across the 4 sibling lanes (same warp)
        float mx = m_r;
        #pragma unroll
        for (int jj = 0; jj < 16; jj++) mx = fmaxf(mx, sc[jj]);
        mx = fmaxf(mx, __shfl_xor_sync(0xffffffffu, mx, 1));
        mx = fmaxf(mx, __shfl_xor_sync(0xffffffffu, mx, 2));

        float alpha = __expf(m_r - mx);
        float psum = 0.0f;
        #pragma unroll
        for (int jj = 0; jj < 16; jj++) {
            float p = __expf(sc[jj] - mx);
            psum += p;
            Ss[r * ATTN_PAD + (jj << 2) + seg] = p;
        }
        psum += __shfl_xor_sync(0xffffffffu, psum, 1);
        psum += __shfl_xor_sync(0xffffffffu, psum, 2);
        l_r = l_r * alpha + psum;
        #pragma unroll
        for (int i = 0; i < 16; i++) oacc[i] *= alpha;

        __syncwarp();   // Ss row written/read by 4 lanes of the same warp

        // O += P @ V   (this thread owns d = seg*16 .. seg*16+15)
        #pragma unroll 4
        for (int j = 0; j < 64; j++) {
            float p = Ss[r * ATTN_PAD + j];
            const float* vptr = &Vs[j * ATTN_PAD + (seg << 4)];
            #pragma unroll
            for (int dd = 0; dd < 16; dd++)
                oacc[dd] = fmaf(p, vptr[dd], oacc[dd]);
        }
        m_r = mx;
    }

    float inv = 1.0f / l_r;
    float* optr = &og[(rowbase + qglob) * DMODEL + col0 + (seg << 4)];
    #pragma unroll
    for (int dd = 0; dd < 16; dd += 4) {
        float4 t = make_float4(oacc[dd] * inv, oacc[dd+1] * inv,
                               oacc[dd+2] * inv, oacc[dd+3] * inv);
        *(float4*)&optr[dd] = t;
    }
}

// ---------------------------------------------------------------------------
// Host launcher.  Graph-capturable: kernel launches only.
// ---------------------------------------------------------------------------
extern "C" void kernel_launch(void* const* d_in, const int* in_sizes, int n_in,
                              void* d_out, int out_size)
{
    const int*   tokens = (const int*)  d_in[0];
    const float* emb    = (const float*)d_in[1];
    const float* pos    = (const float*)d_in[2];
    const float* Wq     = (const float*)d_in[3];
    const float* bq     = (const float*)d_in[4];
    const float* Wk     = (const float*)d_in[5];
    const float* bk     = (const float*)d_in[6];
    const float* Wv     = (const float*)d_in[7];
    const float* bv     = (const float*)d_in[8];
    const float* Wo     = (const float*)d_in[9];
    const float* bo     = (const float*)d_in[10];
    const float* ln1g   = (const float*)d_in[11];
    const float* ln1b   = (const float*)d_in[12];
    const float* W1     = (const float*)d_in[13];
    const float* b1     = (const float*)d_in[14];
    const float* W2     = (const float*)d_in[15];
    const float* b2     = (const float*)d_in[16];
    const float* ln2g   = (const float*)d_in[17];
    const float* ln2b   = (const float*)d_in[18];
    const float* lnfg   = (const float*)d_in[19];
    const float* lnfb   = (const float*)d_in[20];
    const float* Whead  = (const float*)d_in[21];
    const float* bhead  = (const float*)d_in[22];
    float* out = (float*)d_out;

    float *x, *h, *q, *k, *v, *ao, *ff;
    cudaGetSymbolAddress((void**)&x,  g_x);
    cudaGetSymbolAddress((void**)&h,  g_h);
    cudaGetSymbolAddress((void**)&q,  g_q);
    cudaGetSymbolAddress((void**)&k,  g_k);
    cudaGetSymbolAddress((void**)&v,  g_v);
    cudaGetSymbolAddress((void**)&ao, g_ao);
    cudaGetSymbolAddress((void**)&ff, g_ff);

    cudaFuncSetAttribute(attn_kernel,
                         cudaFuncAttributeMaxDynamicSharedMemorySize,
                         ATTN_SMEM_BYTES);

    embed_kernel<<<NROWS, 128>>>(tokens, emb, pos, x);

    const dim3 gD((DMODEL + 63) / 64, NROWS / 128);      // N=512  -> (8,16)
    const dim3 gF((DFF + 63) / 64, NROWS / 128);         // N=2048 -> (32,16)
    const dim3 gV((VOCAB + 63) / 64, NROWS / 128);       // N=50257-> (786,16)

    for (int l = 0; l < NLAYER; l++) {
        const size_t wD = (size_t)l * DMODEL * DMODEL;
        const size_t vD = (size_t)l * DMODEL;
        const size_t wF = (size_t)l * DFF * DMODEL;
        const size_t vF = (size_t)l * DFF;

        // pre-norm attention
        ln_kernel<<<NROWS, 128>>>(x, ln1g + vD, ln1b + vD, h);
        sgemm_nt<false,false><<<gD, 128>>>(h, Wq + wD, bq + vD, nullptr, q, NROWS, DMODEL, DMODEL);
        sgemm_nt<false,false><<<gD, 128>>>(h, Wk + wD, bk + vD, nullptr, k, NROWS, DMODEL, DMODEL);
        sgemm_nt<false,false><<<gD, 128>>>(h, Wv + wD, bv + vD, nullptr, v, NROWS, DMODEL, DMODEL);
        attn_kernel<<<dim3(16, 16), 256, ATTN_SMEM_BYTES>>>(q, k, v, ao);
        // x = x + ao @ Wo^T + bo   (residual fused, in-place on x: 1:1 read/write)
        sgemm_nt<false,true><<<gD, 128>>>(ao, Wo + wD, bo + vD, x, x, NROWS, DMODEL, DMODEL);

        // pre-norm FFN
        ln_kernel<<<NROWS, 128>>>(x, ln2g + vD, ln2b + vD, h);
        sgemm_nt<true,false><<<gF, 128>>>(h, W1 + wF, b1 + vF, nullptr, ff, NROWS, DFF, DMODEL);
        sgemm_nt<false,true><<<gD, 128>>>(ff, W2 + (size_t)l * DMODEL * DFF, b2 + vD, x, x, NROWS, DMODEL, DFF);
    }

    ln_kernel<<<NROWS, 128>>>(x, lnfg, lnfb, h);
    sgemm_nt<false,false><<<gV, 128>>>(h, Whead, bhead, nullptr, out, NROWS, VOCAB, DMODEL);
}

// round 4
// speedup vs baseline: 1.5713x; 1.5713x over previous
#include <cuda_runtime.h>
#include <cuda_bf16.h>
#include <math.h>
#include <stdint.h>

// ---------------------------------------------------------------------------
// ManifoldTransformer on GB300 via generic-ISA tensor cores (mma.sync bf16,
// fp32 accumulate). 3-term hi/lo bf16 split along K for fp32-class accuracy:
//   A stream per k: (Ah, Al, Ah) ; B stream per k: (Bh, Bh, Bl)
//   sum over K3=3K  ->  Ah*Bh + Al*Bh + Ah*Bl   (error ~ Al*Bl ~ 4e-6)
// B=2,S=1024,D=512,H=8,DFF=2048,L=4,V=50257.
// ---------------------------------------------------------------------------

#define NROWS 2048
#define DMODEL 512
#define DFF 2048
#define NLAYER 4
#define VOCAB 50257
#define SEQ 1024
#define QKV_LD 1536

#define K3_D  (3 * DMODEL)   // 1536
#define K3_F  (3 * DFF)      // 6144

// ---------------- scratch (device globals: allocation-free) -----------------
__device__ __align__(256) float g_x  [NROWS * DMODEL];
__device__ __align__(256) float g_qkv[NROWS * QKV_LD];
__device__ __align__(256) __nv_bfloat16 g_h3 [NROWS * K3_D];
__device__ __align__(256) __nv_bfloat16 g_ao3[NROWS * K3_D];
__device__ __align__(256) __nv_bfloat16 g_ff3[NROWS * K3_F];
// triple-split weights (order h,h,l along K3)
__device__ __align__(256) __nv_bfloat16 g_wqkv[NLAYER * QKV_LD * K3_D];
__device__ __align__(256) __nv_bfloat16 g_wo  [NLAYER * DMODEL * K3_D];
__device__ __align__(256) __nv_bfloat16 g_w1  [NLAYER * DFF    * K3_D];
__device__ __align__(256) __nv_bfloat16 g_w2  [NLAYER * DMODEL * K3_F];
__device__ __align__(256) __nv_bfloat16 g_wh  [(size_t)VOCAB   * K3_D];
__device__ __align__(256) float g_bqkv[NLAYER * QKV_LD];

// ---------------- helpers ----------------------------------------------------
__device__ __forceinline__ uint32_t smem_u32(const void* p) {
    uint32_t a;
    asm("{ .reg .u64 t; cvta.to.shared.u64 t, %1; cvt.u32.u64 %0, t; }"
        : "=r"(a) : "l"(p));
    return a;
}
__device__ __forceinline__ void ldsm4(uint32_t* r, uint32_t addr) {
    asm volatile("ldmatrix.sync.aligned.m8n8.x4.shared.b16 {%0,%1,%2,%3}, [%4];"
        : "=r"(r[0]), "=r"(r[1]), "=r"(r[2]), "=r"(r[3]) : "r"(addr));
}
__device__ __forceinline__ void mma16816(float* d, const uint32_t* a, const uint32_t* b) {
    asm volatile("mma.sync.aligned.m16n8k16.row.col.f32.bf16.bf16.f32 "
        "{%0,%1,%2,%3}, {%4,%5,%6,%7}, {%8,%9}, {%0,%1,%2,%3};"
        : "+f"(d[0]), "+f"(d[1]), "+f"(d[2]), "+f"(d[3])
        : "r"(a[0]), "r"(a[1]), "r"(a[2]), "r"(a[3]), "r"(b[0]), "r"(b[1]));
}
__device__ __forceinline__ __nv_bfloat162 split1(float x) {
    __nv_bfloat162 r;
    r.x = __float2bfloat16(x);
    r.y = __float2bfloat16(x - __bfloat162float(r.x));
    return r;
}

// ---------------- weight split: per element emit (h, h, l) ------------------
__global__ void wsplit3_kernel(const float* __restrict__ src,
                               __nv_bfloat16* __restrict__ dst, long n8)
{
    long i = (long)blockIdx.x * 256 + threadIdx.x;
    if (i >= n8) return;
    float4 v0 = *(const float4*)(src + i * 8);
    float4 v1 = *(const float4*)(src + i * 8 + 4);
    union { __nv_bfloat16 h[24]; uint4 u[3]; } P;
    const float vv[8] = {v0.x, v0.y, v0.z, v0.w, v1.x, v1.y, v1.z, v1.w};
    #pragma unroll
    for (int e = 0; e < 8; e++) {
        __nv_bfloat162 s = split1(vv[e]);
        P.h[e * 3 + 0] = s.x;
        P.h[e * 3 + 1] = s.x;
        P.h[e * 3 + 2] = s.y;
    }
    uint4* q = (uint4*)(dst + i * 24);
    q[0] = P.u[0]; q[1] = P.u[1]; q[2] = P.u[2];
}

// ---------------- embedding -------------------------------------------------
__global__ void embed_kernel(const int* __restrict__ tok,
                             const float* __restrict__ emb,
                             const float* __restrict__ pos,
                             float* __restrict__ x)
{
    int row = blockIdx.x, tid = threadIdx.x;
    int t = tok[row], s = row & (SEQ - 1);
    float4 e = *(const float4*)&emb[(size_t)t * DMODEL + tid * 4];
    float4 p = *(const float4*)&pos[(size_t)s * DMODEL + tid * 4];
    e.x += p.x; e.y += p.y; e.z += p.z; e.w += p.w;
    *(float4*)&x[(size_t)row * DMODEL + tid * 4] = e;
}

// ---------------- LayerNorm -> triple bf16 (h,l,h) ---------------------------
__global__ void ln_kernel(const float* __restrict__ x,
                          const float* __restrict__ g,
                          const float* __restrict__ b,
                          __nv_bfloat16* __restrict__ y3)
{
    __shared__ float red[4];
    __shared__ float bc;
    int row = blockIdx.x, tid = threadIdx.x;
    int lane = tid & 31, w = tid >> 5;

    float4 v = *(const float4*)&x[(size_t)row * DMODEL + tid * 4];
    float s = v.x + v.y + v.z + v.w;
    #pragma unroll
    for (int o = 16; o; o >>= 1) s += __shfl_xor_sync(0xffffffffu, s, o);
    if (lane == 0) red[w] = s;
    __syncthreads();
    if (tid == 0) bc = (red[0] + red[1] + red[2] + red[3]) * (1.0f / 512.0f);
    __syncthreads();
    float mean = bc;
    float dx = v.x - mean, dy = v.y - mean, dz = v.z - mean, dw = v.w - mean;
    float s2 = dx*dx + dy*dy + dz*dz + dw*dw;
    #pragma unroll
    for (int o = 16; o; o >>= 1) s2 += __shfl_xor_sync(0xffffffffu, s2, o);
    __syncthreads();
    if (lane == 0) red[w] = s2;
    __syncthreads();
    if (tid == 0) bc = rsqrtf((red[0] + red[1] + red[2] + red[3]) * (1.0f / 512.0f) + 1e-5f);
    __syncthreads();
    float inv = bc;

    float4 gg = *(const float4*)&g[tid * 4];
    float4 bb = *(const float4*)&b[tid * 4];
    float ov[4];
    ov[0] = dx * inv * gg.x + bb.x;
    ov[1] = dy * inv * gg.y + bb.y;
    ov[2] = dz * inv * gg.z + bb.z;
    ov[3] = dw * inv * gg.w + bb.w;
    union { __nv_bfloat16 h[12]; uint2 u[3]; } P;
    #pragma unroll
    for (int e = 0; e < 4; e++) {
        __nv_bfloat162 sp = split1(ov[e]);
        P.h[e * 3 + 0] = sp.x;
        P.h[e * 3 + 1] = sp.y;
        P.h[e * 3 + 2] = sp.x;
    }
    uint2* q = (uint2*)(y3 + (size_t)row * K3_D + tid * 12);
    q[0] = P.u[0]; q[1] = P.u[1]; q[2] = P.u[2];
}

// ---------------------------------------------------------------------------
// HMMA GEMM: C[M,N] = A[M,K3]_bf16 @ B[N,K3]_bf16^T, fp32 accum.
// CTA 128x128, BK=32, 256 threads (8 warps, each 32x64), double-buffered smem.
// smem row stride 40 bf16 (80B): 16B-aligned rows, conflict-free ldmatrix.
// ---------------------------------------------------------------------------
#define SLD 40
#define STILE (128 * SLD * 2)   // 10240 bytes

template<bool GELU, bool RES, bool TRIPLEOUT>
__global__ __launch_bounds__(256, 2)
void hmma_gemm(const __nv_bfloat16* __restrict__ A, const __nv_bfloat16* __restrict__ Bm,
               const float* __restrict__ bias, const float* __restrict__ Rres,
               void* __restrict__ Cout, int N, int K3, int ldc)
{
    __shared__ __align__(16) char sm[4 * STILE];

    const int tid = threadIdx.x;
    const int lane = tid & 31, wid = tid >> 5;
    const int wm = wid & 3, wn = wid >> 2;
    const int m0 = blockIdx.y << 7, n0 = blockIdx.x << 7;

    const int r0 = tid >> 2, c0 = tid & 3;     // loader mapping

    float acc[2][8][4];
    #pragma unroll
    for (int i = 0; i < 2; i++)
        #pragma unroll
        for (int j = 0; j < 8; j++)
            #pragma unroll
            for (int k = 0; k < 4; k++) acc[i][j][k] = 0.0f;

    const int nc = K3 >> 5;
    uint4 ra0, ra1, rb0, rb1;

    auto load_regs = [&](int c) {
        const __nv_bfloat16* Ab = A + (size_t)m0 * K3 + c * 32;
        ra0 = *(const uint4*)(Ab + (size_t)(r0)      * K3 + c0 * 8);
        ra1 = *(const uint4*)(Ab + (size_t)(r0 + 64) * K3 + c0 * 8);
        const __nv_bfloat16* Bb = Bm + (size_t)n0 * K3 + c * 32;
        rb0 = make_uint4(0,0,0,0); rb1 = make_uint4(0,0,0,0);
        if (n0 + r0 < N)      rb0 = *(const uint4*)(Bb + (size_t)(r0)      * K3 + c0 * 8);
        if (n0 + r0 + 64 < N) rb1 = *(const uint4*)(Bb + (size_t)(r0 + 64) * K3 + c0 * 8);
    };
    auto store_smem = [&](int buf) {
        char* sA = sm + buf * (2 * STILE);
        char* sB = sA + STILE;
        *(uint4*)(sA + (r0)      * (SLD*2) + c0 * 16) = ra0;
        *(uint4*)(sA + (r0 + 64) * (SLD*2) + c0 * 16) = ra1;
        *(uint4*)(sB + (r0)      * (SLD*2) + c0 * 16) = rb0;
        *(uint4*)(sB + (r0 + 64) * (SLD*2) + c0 * 16) = rb1;
    };
    auto compute = [&](int buf) {
        uint32_t aBase = smem_u32(sm + buf * (2 * STILE));
        uint32_t bBase = aBase + STILE;
        #pragma unroll
        for (int ks = 0; ks < 2; ks++) {
            uint32_t afrag[2][4];
            #pragma unroll
            for (int mi = 0; mi < 2; mi++) {
                int arow = wm * 32 + mi * 16 + (lane & 15);
                int acol = ks * 16 + ((lane >> 4) << 3);
                ldsm4(afrag[mi], aBase + arow * (SLD*2) + acol * 2);
            }
            uint32_t bfrag[4][4];
            #pragma unroll
            for (int ni = 0; ni < 4; ni++) {
                int brow = wn * 64 + ni * 16 + (lane & 7) + ((lane >> 4) << 3);
                int bcol = ks * 16 + (((lane >> 3) & 1) << 3);
                ldsm4(bfrag[ni], bBase + brow * (SLD*2) + bcol * 2);
            }
            #pragma unroll
            for (int mi = 0; mi < 2; mi++)
                #pragma unroll
                for (int t = 0; t < 8; t++)
                    mma16816(acc[mi][t], afrag[mi], &bfrag[t >> 1][(t & 1) * 2]);
        }
    };

    load_regs(0);
    store_smem(0);
    __syncthreads();
    for (int c = 0; c < nc; c++) {
        int buf = c & 1;
        if (c + 1 < nc) load_regs(c + 1);
        compute(buf);
        if (c + 1 < nc) {
            store_smem(buf ^ 1);
            __syncthreads();
        }
    }

    // epilogue
    #pragma unroll
    for (int mi = 0; mi < 2; mi++) {
        #pragma unroll
        for (int t = 0; t < 8; t++) {
            int gmA = m0 + wm * 32 + mi * 16 + (lane >> 2);
            int gn  = n0 + wn * 64 + t * 8 + ((lane & 3) << 1);
            #pragma unroll
            for (int half = 0; half < 2; half++) {
                int gm = gmA + half * 8;
                #pragma unroll
                for (int cc = 0; cc < 2; cc++) {
                    int g = gn + cc;
                    if (g < N) {
                        float v = acc[mi][t][half * 2 + cc] + bias[g];
                        if (GELU) v = 0.5f * v * (1.0f + erff(v * 0.70710678118654752f));
                        if (RES)  v += Rres[(size_t)gm * ldc + g];
                        if (TRIPLEOUT) {
                            __nv_bfloat16* o = (__nv_bfloat16*)Cout;
                            size_t bidx = ((size_t)gm * ldc + g) * 3;
                            __nv_bfloat162 sp = split1(v);
                            o[bidx] = sp.x; o[bidx + 1] = sp.y; o[bidx + 2] = sp.x;
                        } else {
                            ((float*)Cout)[(size_t)gm * ldc + g] = v;
                        }
                    }
                }
            }
        }
    }
}

// ---------------------------------------------------------------------------
// Flash-style causal attention (fp32 from fused qkv, stride 1536).
// Output: triple bf16 (h,l,h) into ao3.
// ---------------------------------------------------------------------------
#define ATTN_PAD 68
#define ATTN_SMEM_BYTES (3 * 64 * ATTN_PAD * 4)

__global__ __launch_bounds__(256)
void attn_kernel(const float* __restrict__ qkv, __nv_bfloat16* __restrict__ og3)
{
    extern __shared__ float smf[];
    float* Ks = smf;
    float* Vs = smf + 64 * ATTN_PAD;
    float* Ss = smf + 2 * 64 * ATTN_PAD;

    const int qb = blockIdx.x, bh = blockIdx.y;
    const int b = bh >> 3, h = bh & 7;
    const int tid = threadIdx.x;
    const int r = tid >> 2, seg = tid & 3;
    const int rowbase = b << 10;
    const int col0 = h << 6;
    const int qglob = (qb << 6) + r;

    float qreg[64];
    {
        const float* qptr = &qkv[(size_t)(rowbase + qglob) * QKV_LD + col0];
        #pragma unroll
        for (int i = 0; i < 16; i++) {
            float4 t = *(const float4*)&qptr[i * 4];
            qreg[i*4+0] = t.x; qreg[i*4+1] = t.y; qreg[i*4+2] = t.z; qreg[i*4+3] = t.w;
        }
    }

    float m_r = -3e38f, l_r = 0.0f;
    float oacc[16];
    #pragma unroll
    for (int i = 0; i < 16; i++) oacc[i] = 0.0f;

    for (int kb = 0; kb <= qb; kb++) {
        __syncthreads();
        for (int i = tid; i < 1024; i += 256) {
            int rr = i >> 4, c4 = (i & 15) << 2;
            size_t g = (size_t)(rowbase + (kb << 6) + rr) * QKV_LD + col0 + c4;
            float4 tk = *(const float4*)&qkv[g + DMODEL];
            float4 tv = *(const float4*)&qkv[g + 2 * DMODEL];
            *(float4*)&Ks[rr * ATTN_PAD + c4] = tk;
            *(float4*)&Vs[rr * ATTN_PAD + c4] = tv;
        }
        __syncthreads();

        float sc[16];
        #pragma unroll 4
        for (int jj = 0; jj < 16; jj++) {
            int kc = (jj << 2) + seg;
            const float* kptr = &Ks[kc * ATTN_PAD];
            float a0 = 0.0f;
            #pragma unroll
            for (int d = 0; d < 64; d++) a0 = fmaf(qreg[d], kptr[d], a0);
            a0 *= 0.125f;
            if ((kb << 6) + kc > qglob) a0 = -3e38f;
            sc[jj] = a0;
        }

        float mx = m_r;
        #pragma unroll
        for (int jj = 0; jj < 16; jj++) mx = fmaxf(mx, sc[jj]);
        mx = fmaxf(mx, __shfl_xor_sync(0xffffffffu, mx, 1));
        mx = fmaxf(mx, __shfl_xor_sync(0xffffffffu, mx, 2));

        float alpha = __expf(m_r - mx);
        float psum = 0.0f;
        #pragma unroll
        for (int jj = 0; jj < 16; jj++) {
            float p = __expf(sc[jj] - mx);
            psum += p;
            Ss[r * ATTN_PAD + (jj << 2) + seg] = p;
        }
        psum += __shfl_xor_sync(0xffffffffu, psum, 1);
        psum += __shfl_xor_sync(0xffffffffu, psum, 2);
        l_r = l_r * alpha + psum;
        #pragma unroll
        for (int i = 0; i < 16; i++) oacc[i] *= alpha;

        __syncwarp();

        #pragma unroll 4
        for (int j = 0; j < 64; j++) {
            float p = Ss[r * ATTN_PAD + j];
            const float* vptr = &Vs[j * ATTN_PAD + (seg << 4)];
            #pragma unroll
            for (int dd = 0; dd < 16; dd++)
                oacc[dd] = fmaf(p, vptr[dd], oacc[dd]);
        }
        m_r = mx;
    }

    float inv = 1.0f / l_r;
    union { __nv_bfloat16 h[48]; uint4 u[6]; } P;
    #pragma unroll
    for (int e = 0; e < 16; e++) {
        __nv_bfloat162 sp = split1(oacc[e] * inv);
        P.h[e * 3 + 0] = sp.x;
        P.h[e * 3 + 1] = sp.y;
        P.h[e * 3 + 2] = sp.x;
    }
    uint4* q = (uint4*)(og3 + (size_t)(rowbase + qglob) * K3_D
                            + (size_t)(col0 + (seg << 4)) * 3);
    #pragma unroll
    for (int i = 0; i < 6; i++) q[i] = P.u[i];
}

// ---------------------------------------------------------------------------
// Host launcher (graph-capturable).
// ---------------------------------------------------------------------------
extern "C" void kernel_launch(void* const* d_in, const int* in_sizes, int n_in,
                              void* d_out, int out_size)
{
    const int*   tokens = (const int*)  d_in[0];
    const float* emb    = (const float*)d_in[1];
    const float* pos    = (const float*)d_in[2];
    const float* Wq     = (const float*)d_in[3];
    const float* bq     = (const float*)d_in[4];
    const float* Wk     = (const float*)d_in[5];
    const float* bk     = (const float*)d_in[6];
    const float* Wv     = (const float*)d_in[7];
    const float* bv     = (const float*)d_in[8];
    const float* Wo     = (const float*)d_in[9];
    const float* bo     = (const float*)d_in[10];
    const float* ln1g   = (const float*)d_in[11];
    const float* ln1b   = (const float*)d_in[12];
    const float* W1     = (const float*)d_in[13];
    const float* b1     = (const float*)d_in[14];
    const float* W2     = (const float*)d_in[15];
    const float* b2     = (const float*)d_in[16];
    const float* ln2g   = (const float*)d_in[17];
    const float* ln2b   = (const float*)d_in[18];
    const float* lnfg   = (const float*)d_in[19];
    const float* lnfb   = (const float*)d_in[20];
    const float* Whead  = (const float*)d_in[21];
    const float* bhead  = (const float*)d_in[22];
    float* out = (float*)d_out;

    float *x, *qkv, *bqkv;
    __nv_bfloat16 *h3, *ao3, *ff3, *wqkv, *wo, *w1, *w2, *wh;
    cudaGetSymbolAddress((void**)&x,    g_x);
    cudaGetSymbolAddress((void**)&qkv,  g_qkv);
    cudaGetSymbolAddress((void**)&bqkv, g_bqkv);
    cudaGetSymbolAddress((void**)&h3,   g_h3);
    cudaGetSymbolAddress((void**)&ao3,  g_ao3);
    cudaGetSymbolAddress((void**)&ff3,  g_ff3);
    cudaGetSymbolAddress((void**)&wqkv, g_wqkv);
    cudaGetSymbolAddress((void**)&wo,   g_wo);
    cudaGetSymbolAddress((void**)&w1,   g_w1);
    cudaGetSymbolAddress((void**)&w2,   g_w2);
    cudaGetSymbolAddress((void**)&wh,   g_wh);

    cudaFuncSetAttribute(attn_kernel, cudaFuncAttributeMaxDynamicSharedMemorySize, ATTN_SMEM_BYTES);

    // ---- weight conversion to triple bf16 (h,h,l) ----
    auto wsplit = [](const float* s, __nv_bfloat16* d, size_t n) {
        long n8 = (long)(n / 8);
        wsplit3_kernel<<<(unsigned)((n8 + 255) / 256), 256>>>(s, d, n8);
    };
    const size_t DD = (size_t)DMODEL * DMODEL;
    const size_t FD = (size_t)DFF * DMODEL;
    for (int l = 0; l < NLAYER; l++) {
        wsplit(Wq + l * DD, wqkv + (size_t)l * QKV_LD * K3_D + (size_t)0    * K3_D, DD);
        wsplit(Wk + l * DD, wqkv + (size_t)l * QKV_LD * K3_D + (size_t)512  * K3_D, DD);
        wsplit(Wv + l * DD, wqkv + (size_t)l * QKV_LD * K3_D + (size_t)1024 * K3_D, DD);
        wsplit(Wo + l * DD, wo   + (size_t)l * DMODEL * K3_D, DD);
        wsplit(W1 + l * FD, w1   + (size_t)l * DFF    * K3_D, FD);
        wsplit(W2 + l * FD, w2   + (size_t)l * DMODEL * K3_F, FD);
        cudaMemcpyAsync(bqkv + l * QKV_LD +    0, bq + l * DMODEL, DMODEL * 4, cudaMemcpyDeviceToDevice);
        cudaMemcpyAsync(bqkv + l * QKV_LD +  512, bk + l * DMODEL, DMODEL * 4, cudaMemcpyDeviceToDevice);
        cudaMemcpyAsync(bqkv + l * QKV_LD + 1024, bv + l * DMODEL, DMODEL * 4, cudaMemcpyDeviceToDevice);
    }
    wsplit(Whead, wh, (size_t)VOCAB * DMODEL);

    embed_kernel<<<NROWS, 128>>>(tokens, emb, pos, x);

    const dim3 gQKV(QKV_LD / 128, NROWS / 128);           // (12,16)
    const dim3 gD  (DMODEL / 128, NROWS / 128);           // (4,16)
    const dim3 gF  (DFF / 128,    NROWS / 128);           // (16,16)
    const dim3 gV  ((VOCAB + 127) / 128, NROWS / 128);    // (393,16)

    for (int l = 0; l < NLAYER; l++) {
        const size_t vD = (size_t)l * DMODEL;

        ln_kernel<<<NROWS, 128>>>(x, ln1g + vD, ln1b + vD, h3);
        hmma_gemm<false,false,false><<<gQKV, 256>>>(
            h3, wqkv + (size_t)l * QKV_LD * K3_D, bqkv + l * QKV_LD, nullptr,
            qkv, QKV_LD, K3_D, QKV_LD);
        attn_kernel<<<dim3(16, 16), 256, ATTN_SMEM_BYTES>>>(qkv, ao3);
        hmma_gemm<false,true,false><<<gD, 256>>>(
            ao3, wo + (size_t)l * DMODEL * K3_D, bo + vD, x,
            x, DMODEL, K3_D, DMODEL);

        ln_kernel<<<NROWS, 128>>>(x, ln2g + vD, ln2b + vD, h3);
        hmma_gemm<true,false,true><<<gF, 256>>>(
            h3, w1 + (size_t)l * DFF * K3_D, b1 + (size_t)l * DFF, nullptr,
            ff3, DFF, K3_D, DFF);
        hmma_gemm<false,true,false><<<gD, 256>>>(
            ff3, w2 + (size_t)l * DMODEL * K3_F, b2 + vD, x,
            x, DMODEL, K3_F, DMODEL);
    }

    ln_kernel<<<NROWS, 128>>>(x, lnfg, lnfb, h3);
    hmma_gemm<false,false,false><<<gV, 256>>>(
        h3, wh, bhead, nullptr, out, VOCAB, K3_D, VOCAB);
}

// round 5
// speedup vs baseline: 1.7332x; 1.1030x over previous
#include <cuda_runtime.h>
#include <cuda_bf16.h>
#include <math.h>
#include <stdint.h>

// ---------------------------------------------------------------------------
// ManifoldTransformer on GB300 via mma.sync bf16 (fp32 accumulate), with the
// 3-term hi/lo split fused into the GEMM smem loaders:
//   A stream per k: (Ah, Al, Ah) ; B stream per k: (Bh, Bh, Bl)
//   -> Ah*Bh + Al*Bh + Ah*Bl  (dropped Al*Bl ~ 4e-6 relative)
// All GEMM interfaces are plain fp32. B=2,S=1024,D=512,H=8,DFF=2048,L=4,V=50257.
// ---------------------------------------------------------------------------

#define NROWS 2048
#define DMODEL 512
#define DFF 2048
#define NLAYER 4
#define VOCAB 50257
#define SEQ 1024
#define QKV_LD 1536

// ---------------- scratch (device globals: allocation-free) -----------------
__device__ __align__(256) float g_x  [NROWS * DMODEL];   // residual stream
__device__ __align__(256) float g_h  [NROWS * DMODEL];   // ln output
__device__ __align__(256) float g_ao [NROWS * DMODEL];   // attention output
__device__ __align__(256) float g_ff [NROWS * DFF];      // gelu output
__device__ __align__(256) float g_qkv[NROWS * QKV_LD];   // fused q|k|v
__device__ __align__(256) float g_wqkvf[QKV_LD * DMODEL];// fused qkv weights (per layer)
__device__ __align__(256) float g_bqkv [QKV_LD];         // fused qkv bias (per layer)

// ---------------- helpers ----------------------------------------------------
__device__ __forceinline__ uint32_t smem_u32(const void* p) {
    uint32_t a;
    asm("{ .reg .u64 t; cvta.to.shared.u64 t, %1; cvt.u32.u64 %0, t; }"
        : "=r"(a) : "l"(p));
    return a;
}
__device__ __forceinline__ void ldsm4(uint32_t* r, uint32_t addr) {
    asm volatile("ldmatrix.sync.aligned.m8n8.x4.shared.b16 {%0,%1,%2,%3}, [%4];"
        : "=r"(r[0]), "=r"(r[1]), "=r"(r[2]), "=r"(r[3]) : "r"(addr));
}
__device__ __forceinline__ void mma16816(float* d, const uint32_t* a, const uint32_t* b) {
    asm volatile("mma.sync.aligned.m16n8k16.row.col.f32.bf16.bf16.f32 "
        "{%0,%1,%2,%3}, {%4,%5,%6,%7}, {%8,%9}, {%0,%1,%2,%3};"
        : "+f"(d[0]), "+f"(d[1]), "+f"(d[2]), "+f"(d[3])
        : "r"(a[0]), "r"(a[1]), "r"(a[2]), "r"(a[3]), "r"(b[0]), "r"(b[1]));
}
__device__ __forceinline__ __nv_bfloat162 split1(float x) {
    __nv_bfloat162 r;
    r.x = __float2bfloat16(x);
    r.y = __float2bfloat16(x - __bfloat162float(r.x));
    return r;
}

// ---------------- embedding -------------------------------------------------
__global__ void embed_kernel(const int* __restrict__ tok,
                             const float* __restrict__ emb,
                             const float* __restrict__ pos,
                             float* __restrict__ x)
{
    int row = blockIdx.x, tid = threadIdx.x;
    int t = tok[row], s = row & (SEQ - 1);
    float4 e = *(const float4*)&emb[(size_t)t * DMODEL + tid * 4];
    float4 p = *(const float4*)&pos[(size_t)s * DMODEL + tid * 4];
    e.x += p.x; e.y += p.y; e.z += p.z; e.w += p.w;
    *(float4*)&x[(size_t)row * DMODEL + tid * 4] = e;
}

// ---------------- LayerNorm (fp32 out) ---------------------------------------
__global__ void ln_kernel(const float* __restrict__ x,
                          const float* __restrict__ g,
                          const float* __restrict__ b,
                          float* __restrict__ y)
{
    __shared__ float red[4];
    __shared__ float bc;
    int row = blockIdx.x, tid = threadIdx.x;
    int lane = tid & 31, w = tid >> 5;

    float4 v = *(const float4*)&x[(size_t)row * DMODEL + tid * 4];
    float s = v.x + v.y + v.z + v.w;
    #pragma unroll
    for (int o = 16; o; o >>= 1) s += __shfl_xor_sync(0xffffffffu, s, o);
    if (lane == 0) red[w] = s;
    __syncthreads();
    if (tid == 0) bc = (red[0] + red[1] + red[2] + red[3]) * (1.0f / 512.0f);
    __syncthreads();
    float mean = bc;
    float dx = v.x - mean, dy = v.y - mean, dz = v.z - mean, dw = v.w - mean;
    float s2 = dx*dx + dy*dy + dz*dz + dw*dw;
    #pragma unroll
    for (int o = 16; o; o >>= 1) s2 += __shfl_xor_sync(0xffffffffu, s2, o);
    __syncthreads();
    if (lane == 0) red[w] = s2;
    __syncthreads();
    if (tid == 0) bc = rsqrtf((red[0] + red[1] + red[2] + red[3]) * (1.0f / 512.0f) + 1e-5f);
    __syncthreads();
    float inv = bc;

    float4 gg = *(const float4*)&g[tid * 4];
    float4 bb = *(const float4*)&b[tid * 4];
    float4 o4;
    o4.x = dx * inv * gg.x + bb.x;
    o4.y = dy * inv * gg.y + bb.y;
    o4.z = dz * inv * gg.z + bb.z;
    o4.w = dw * inv * gg.w + bb.w;
    *(float4*)&y[(size_t)row * DMODEL + tid * 4] = o4;
}

// ---------------------------------------------------------------------------
// HMMA GEMM with fused fp32->triple-bf16 split in the loaders.
// C[M,N] = A[M,K]_f32 @ B[N,K]_f32^T (+bias, +gelu, +res), fp32 accumulate.
// CTA 128x128 over split-K3 chunks of 48 (=16 original k). 256 threads,
// 8 warps each 32x64. 3-stage smem ring, smem row stride 56 bf16 (112B).
// ---------------------------------------------------------------------------
#define SROW 112                      // bytes per smem row (56 bf16)
#define TILE (128 * SROW)             // 14336 B per operand tile
#define STAGE (2 * TILE)              // 28672 B per stage (A + B)
#define GSMEM (3 * STAGE)             // 86016 B

template<bool GELU, bool RES>
__global__ __launch_bounds__(256, 2)
void hmma_gemm(const float* __restrict__ A, const float* __restrict__ Bm,
               const float* __restrict__ bias, const float* __restrict__ Rres,
               float* __restrict__ C, int N, int K, int ldc)
{
    extern __shared__ __align__(16) char sm[];

    const int tid = threadIdx.x;
    const int lane = tid & 31, wid = tid >> 5;
    const int wm = wid & 3, wn = wid >> 2;
    const int m0 = blockIdx.y << 7, n0 = blockIdx.x << 7;
    const int lrow = tid >> 1, lhalf = tid & 1;     // loader: 2 threads/row, 8 fp32 each

    float acc[2][8][4];
    #pragma unroll
    for (int i = 0; i < 2; i++)
        #pragma unroll
        for (int j = 0; j < 8; j++)
            #pragma unroll
            for (int k = 0; k < 4; k++) acc[i][j][k] = 0.0f;

    const int nc = K >> 4;
    float a_st[8], b_st[8];
    const bool bvalid = (n0 + lrow < N);

    auto ldg = [&](int c) {
        const float* Ap = A + (size_t)(m0 + lrow) * K + c * 16 + lhalf * 8;
        *(float4*)(a_st)     = *(const float4*)(Ap);
        *(float4*)(a_st + 4) = *(const float4*)(Ap + 4);
        if (bvalid) {
            const float* Bp = Bm + (size_t)(n0 + lrow) * K + c * 16 + lhalf * 8;
            *(float4*)(b_st)     = *(const float4*)(Bp);
            *(float4*)(b_st + 4) = *(const float4*)(Bp + 4);
        } else {
            #pragma unroll
            for (int e = 0; e < 8; e++) b_st[e] = 0.0f;
        }
    };
    auto sts = [&](int stage) {
        char* sA = sm + stage * STAGE;
        char* sB = sA + TILE;
        const int base = lrow * SROW + lhalf * 48;
        union { __nv_bfloat16 h[24]; uint4 u[3]; } P;
        #pragma unroll
        for (int e = 0; e < 8; e++) {              // A pattern (h, l, h)
            __nv_bfloat162 sp = split1(a_st[e]);
            P.h[e * 3 + 0] = sp.x;
            P.h[e * 3 + 1] = sp.y;
            P.h[e * 3 + 2] = sp.x;
        }
        #pragma unroll
        for (int i = 0; i < 3; i++) ((uint4*)(sA + base))[i] = P.u[i];
        #pragma unroll
        for (int e = 0; e < 8; e++) {              // B pattern (h, h, l)
            __nv_bfloat162 sp = split1(b_st[e]);
            P.h[e * 3 + 0] = sp.x;
            P.h[e * 3 + 1] = sp.x;
            P.h[e * 3 + 2] = sp.y;
        }
        #pragma unroll
        for (int i = 0; i < 3; i++) ((uint4*)(sB + base))[i] = P.u[i];
    };
    auto compute = [&](int stage) {
        uint32_t aBase = smem_u32(sm + stage * STAGE);
        uint32_t bBase = aBase + TILE;
        #pragma unroll
        for (int ks = 0; ks < 3; ks++) {
            uint32_t afrag[2][4];
            #pragma unroll
            for (int mi = 0; mi < 2; mi++) {
                int arow = wm * 32 + mi * 16 + (lane & 15);
                int abyte = ks * 32 + ((lane >> 4) << 4);
                ldsm4(afrag[mi], aBase + arow * SROW + abyte);
            }
            uint32_t bfrag[4][4];
            #pragma unroll
            for (int ni = 0; ni < 4; ni++) {
                int brow = wn * 64 + ni * 16 + (lane & 7) + ((lane >> 4) << 3);
                int bbyte = ks * 32 + (((lane >> 3) & 1) << 4);
                ldsm4(bfrag[ni], bBase + brow * SROW + bbyte);
            }
            #pragma unroll
            for (int mi = 0; mi < 2; mi++)
                #pragma unroll
                for (int t = 0; t < 8; t++)
                    mma16816(acc[mi][t], afrag[mi], &bfrag[t >> 1][(t & 1) * 2]);
        }
    };

    ldg(0);
    sts(0);
    if (nc > 1) ldg(1);
    __syncthreads();
    for (int c = 0; c < nc; c++) {
        if (c + 1 < nc) sts((c + 1) % 3);
        if (c + 2 < nc) ldg(c + 2);
        compute(c % 3);
        __syncthreads();
    }

    // epilogue
    #pragma unroll
    for (int mi = 0; mi < 2; mi++) {
        #pragma unroll
        for (int t = 0; t < 8; t++) {
            int gmA = m0 + wm * 32 + mi * 16 + (lane >> 2);
            int gn  = n0 + wn * 64 + t * 8 + ((lane & 3) << 1);
            #pragma unroll
            for (int half = 0; half < 2; half++) {
                int gm = gmA + half * 8;
                #pragma unroll
                for (int cc = 0; cc < 2; cc++) {
                    int g = gn + cc;
                    if (g < N) {
                        float v = acc[mi][t][half * 2 + cc] + bias[g];
                        if (GELU) v = 0.5f * v * (1.0f + erff(v * 0.70710678118654752f));
                        if (RES)  v += Rres[(size_t)gm * ldc + g];
                        C[(size_t)gm * ldc + g] = v;
                    }
                }
            }
        }
    }
}

// ---------------------------------------------------------------------------
// Flash-style causal attention (fp32, fused qkv stride 1536, fp32 out).
// ---------------------------------------------------------------------------
#define ATTN_PAD 68
#define ATTN_SMEM_BYTES (3 * 64 * ATTN_PAD * 4)

__global__ __launch_bounds__(256)
void attn_kernel(const float* __restrict__ qkv, float* __restrict__ og)
{
    extern __shared__ float smf[];
    float* Ks = smf;
    float* Vs = smf + 64 * ATTN_PAD;
    float* Ss = smf + 2 * 64 * ATTN_PAD;

    const int qb = blockIdx.x, bh = blockIdx.y;
    const int b = bh >> 3, h = bh & 7;
    const int tid = threadIdx.x;
    const int r = tid >> 2, seg = tid & 3;
    const int rowbase = b << 10;
    const int col0 = h << 6;
    const int qglob = (qb << 6) + r;

    float qreg[64];
    {
        const float* qptr = &qkv[(size_t)(rowbase + qglob) * QKV_LD + col0];
        #pragma unroll
        for (int i = 0; i < 16; i++) {
            float4 t = *(const float4*)&qptr[i * 4];
            qreg[i*4+0] = t.x; qreg[i*4+1] = t.y; qreg[i*4+2] = t.z; qreg[i*4+3] = t.w;
        }
    }

    float m_r = -3e38f, l_r = 0.0f;
    float oacc[16];
    #pragma unroll
    for (int i = 0; i < 16; i++) oacc[i] = 0.0f;

    for (int kb = 0; kb <= qb; kb++) {
        __syncthreads();
        for (int i = tid; i < 1024; i += 256) {
            int rr = i >> 4, c4 = (i & 15) << 2;
            size_t g = (size_t)(rowbase + (kb << 6) + rr) * QKV_LD + col0 + c4;
            float4 tk = *(const float4*)&qkv[g + DMODEL];
            float4 tv = *(const float4*)&qkv[g + 2 * DMODEL];
            *(float4*)&Ks[rr * ATTN_PAD + c4] = tk;
            *(float4*)&Vs[rr * ATTN_PAD + c4] = tv;
        }
        __syncthreads();

        float sc[16];
        #pragma unroll 4
        for (int jj = 0; jj < 16; jj++) {
            int kc = (jj << 2) + seg;
            const float* kptr = &Ks[kc * ATTN_PAD];
            float a0 = 0.0f;
            #pragma unroll
            for (int d = 0; d < 64; d++) a0 = fmaf(qreg[d], kptr[d], a0);
            a0 *= 0.125f;
            if ((kb << 6) + kc > qglob) a0 = -3e38f;
            sc[jj] = a0;
        }

        float mx = m_r;
        #pragma unroll
        for (int jj = 0; jj < 16; jj++) mx = fmaxf(mx, sc[jj]);
        mx = fmaxf(mx, __shfl_xor_sync(0xffffffffu, mx, 1));
        mx = fmaxf(mx, __shfl_xor_sync(0xffffffffu, mx, 2));

        float alpha = __expf(m_r - mx);
        float psum = 0.0f;
        #pragma unroll
        for (int jj = 0; jj < 16; jj++) {
            float p = __expf(sc[jj] - mx);
            psum += p;
            Ss[r * ATTN_PAD + (jj << 2) + seg] = p;
        }
        psum += __shfl_xor_sync(0xffffffffu, psum, 1);
        psum += __shfl_xor_sync(0xffffffffu, psum, 2);
        l_r = l_r * alpha + psum;
        #pragma unroll
        for (int i = 0; i < 16; i++) oacc[i] *= alpha;

        __syncwarp();

        #pragma unroll 4
        for (int j = 0; j < 64; j++) {
            float p = Ss[r * ATTN_PAD + j];
            const float* vptr = &Vs[j * ATTN_PAD + (seg << 4)];
            #pragma unroll
            for (int dd = 0; dd < 16; dd++)
                oacc[dd] = fmaf(p, vptr[dd], oacc[dd]);
        }
        m_r = mx;
    }

    float inv = 1.0f / l_r;
    float* optr = &og[(size_t)(rowbase + qglob) * DMODEL + col0 + (seg << 4)];
    #pragma unroll
    for (int dd = 0; dd < 16; dd += 4) {
        float4 t = make_float4(oacc[dd] * inv, oacc[dd+1] * inv,
                               oacc[dd+2] * inv, oacc[dd+3] * inv);
        *(float4*)&optr[dd] = t;
    }
}

// ---------------------------------------------------------------------------
// Host launcher (graph-capturable).
// ---------------------------------------------------------------------------
extern "C" void kernel_launch(void* const* d_in, const int* in_sizes, int n_in,
                              void* d_out, int out_size)
{
    const int*   tokens = (const int*)  d_in[0];
    const float* emb    = (const float*)d_in[1];
    const float* pos    = (const float*)d_in[2];
    const float* Wq     = (const float*)d_in[3];
    const float* bq     = (const float*)d_in[4];
    const float* Wk     = (const float*)d_in[5];
    const float* bk     = (const float*)d_in[6];
    const float* Wv     = (const float*)d_in[7];
    const float* bv     = (const float*)d_in[8];
    const float* Wo     = (const float*)d_in[9];
    const float* bo     = (const float*)d_in[10];
    const float* ln1g   = (const float*)d_in[11];
    const float* ln1b   = (const float*)d_in[12];
    const float* W1     = (const float*)d_in[13];
    const float* b1     = (const float*)d_in[14];
    const float* W2     = (const float*)d_in[15];
    const float* b2     = (const float*)d_in[16];
    const float* ln2g   = (const float*)d_in[17];
    const float* ln2b   = (const float*)d_in[18];
    const float* lnfg   = (const float*)d_in[19];
    const float* lnfb   = (const float*)d_in[20];
    const float* Whead  = (const float*)d_in[21];
    const float* bhead  = (const float*)d_in[22];
    float* out = (float*)d_out;

    float *x, *h, *ao, *ff, *qkv, *wqkvf, *bqkv;
    cudaGetSymbolAddress((void**)&x,     g_x);
    cudaGetSymbolAddress((void**)&h,     g_h);
    cudaGetSymbolAddress((void**)&ao,    g_ao);
    cudaGetSymbolAddress((void**)&ff,    g_ff);
    cudaGetSymbolAddress((void**)&qkv,   g_qkv);
    cudaGetSymbolAddress((void**)&wqkvf, g_wqkvf);
    cudaGetSymbolAddress((void**)&bqkv,  g_bqkv);

    cudaFuncSetAttribute(attn_kernel, cudaFuncAttributeMaxDynamicSharedMemorySize, ATTN_SMEM_BYTES);
    cudaFuncSetAttribute(hmma_gemm<false,false>, cudaFuncAttributeMaxDynamicSharedMemorySize, GSMEM);
    cudaFuncSetAttribute(hmma_gemm<false,true >, cudaFuncAttributeMaxDynamicSharedMemorySize, GSMEM);
    cudaFuncSetAttribute(hmma_gemm<true ,false>, cudaFuncAttributeMaxDynamicSharedMemorySize, GSMEM);

    embed_kernel<<<NROWS, 128>>>(tokens, emb, pos, x);

    const dim3 gQKV(QKV_LD / 128, NROWS / 128);           // (12,16)
    const dim3 gD  (DMODEL / 128, NROWS / 128);           // (4,16)
    const dim3 gF  (DFF / 128,    NROWS / 128);           // (16,16)
    const dim3 gV  ((VOCAB + 127) / 128, NROWS / 128);    // (393,16)

    const size_t DD = (size_t)DMODEL * DMODEL;
    const size_t FD = (size_t)DFF * DMODEL;

    for (int l = 0; l < NLAYER; l++) {
        const size_t vD = (size_t)l * DMODEL;

        // fused qkv weight + bias staging (graph-capturable D2D copies)
        cudaMemcpyAsync(wqkvf,            Wq + l * DD, DD * 4, cudaMemcpyDeviceToDevice);
        cudaMemcpyAsync(wqkvf + DD,       Wk + l * DD, DD * 4, cudaMemcpyDeviceToDevice);
        cudaMemcpyAsync(wqkvf + 2 * DD,   Wv + l * DD, DD * 4, cudaMemcpyDeviceToDevice);
        cudaMemcpyAsync(bqkv,             bq + vD, DMODEL * 4, cudaMemcpyDeviceToDevice);
        cudaMemcpyAsync(bqkv + DMODEL,    bk + vD, DMODEL * 4, cudaMemcpyDeviceToDevice);
        cudaMemcpyAsync(bqkv + 2*DMODEL,  bv + vD, DMODEL * 4, cudaMemcpyDeviceToDevice);

        ln_kernel<<<NROWS, 128>>>(x, ln1g + vD, ln1b + vD, h);
        hmma_gemm<false,false><<<gQKV, 256, GSMEM>>>(
            h, wqkvf, bqkv, nullptr, qkv, QKV_LD, DMODEL, QKV_LD);
        attn_kernel<<<dim3(16, 16), 256, ATTN_SMEM_BYTES>>>(qkv, ao);
        hmma_gemm<false,true><<<gD, 256, GSMEM>>>(
            ao, Wo + l * DD, bo + vD, x, x, DMODEL, DMODEL, DMODEL);

        ln_kernel<<<NROWS, 128>>>(x, ln2g + vD, ln2b + vD, h);
        hmma_gemm<true,false><<<gF, 256, GSMEM>>>(
            h, W1 + l * FD, b1 + (size_t)l * DFF, nullptr, ff, DFF, DMODEL, DFF);
        hmma_gemm<false,true><<<gD, 256, GSMEM>>>(
            ff, W2 + l * FD, b2 + vD, x, x, DMODEL, DFF, DMODEL);
    }

    ln_kernel<<<NROWS, 128>>>(x, lnfg, lnfb, h);
    hmma_gemm<false,false><<<gV, 256, GSMEM>>>(
        h, Whead, bhead, nullptr, out, VOCAB, DMODEL, VOCAB);
}